// round 5
// baseline (speedup 1.0000x reference)
#include <cuda_runtime.h>

// Problem constants
#define B_   256
#define T_   10
#define BT_  2560      // B_*T_
#define HW_  49
#define VD_  512
#define AD_  128
#define HD_  256       // hidden dims for Wb/Wv2/Wa2 outputs

// ---------------------------------------------------------------------------
// Scratch (allocation-free: __device__ globals)
// ---------------------------------------------------------------------------
__device__ float g_aq1[BT_ * VD_];    // relu(af @ Wa1^T + ba1)        [2560,512]
__device__ float g_aq2[BT_ * HD_];    // relu(af @ Wa2^T + ba2)        [2560,256]
__device__ float g_m1 [BT_ * VD_];    // aq1 * mean_hw relu(vq1)       [2560,512]
__device__ float g_scale[BT_ * VD_];  // sigmoid(...)+1                [2560,512]

// ---------------------------------------------------------------------------
// Packed fp32x2 FMA (Blackwell FFMA2 — only reachable via PTX fma.rn.f32x2)
// ---------------------------------------------------------------------------
__device__ __forceinline__ unsigned long long ffma2(unsigned long long a,
                                                    unsigned long long b,
                                                    unsigned long long c) {
    unsigned long long d;
    asm("fma.rn.f32x2 %0, %1, %2, %3;" : "=l"(d) : "l"(a), "l"(b), "l"(c));
    return d;
}
__device__ __forceinline__ float lo32(unsigned long long v) {
    return __uint_as_float((unsigned)(v & 0xffffffffull));
}
__device__ __forceinline__ float hi32(unsigned long long v) {
    return __uint_as_float((unsigned)(v >> 32));
}

// ---------------------------------------------------------------------------
// K1: audio features. 32 clips per block, 256 threads.
//   af[bt] = audio[t, b, :]  (bt = b*T + t)
//   g_aq1[bt,c] = relu(sum_k af[k]*Wa1[c,k] + ba1[c])   c in [0,512)
//   g_aq2[bt,j] = relu(sum_k af[k]*Wa2[j,k] + ba2[j])   j in [0,256)
// ---------------------------------------------------------------------------
__global__ void __launch_bounds__(256)
k1_audio(const float* __restrict__ audio,
         const float* __restrict__ Wa1, const float* __restrict__ ba1,
         const float* __restrict__ Wa2, const float* __restrict__ ba2)
{
    __shared__ __align__(16) float af[32][AD_];
    const int tid = threadIdx.x;
    const int bt0 = blockIdx.x * 32;

    for (int idx = tid; idx < 32 * AD_; idx += 256) {
        int i = idx >> 7, k = idx & 127;
        int bt = bt0 + i;
        int b = bt / T_, t = bt - b * T_;
        af[i][k] = audio[((size_t)t * B_ + b) * AD_ + k];
    }
    __syncthreads();

    // aq1: 512 outputs, 2 per thread
    for (int c = tid; c < VD_; c += 256) {
        const float4* w4 = (const float4*)(Wa1 + (size_t)c * AD_);
        float acc[32];
#pragma unroll
        for (int i = 0; i < 32; ++i) acc[i] = 0.f;
        for (int k4 = 0; k4 < AD_ / 4; ++k4) {
            float4 w = w4[k4];
#pragma unroll
            for (int i = 0; i < 32; ++i) {
                float4 v = *(const float4*)&af[i][k4 * 4];
                acc[i] += v.x * w.x + v.y * w.y + v.z * w.z + v.w * w.w;
            }
        }
        float bias = ba1[c];
#pragma unroll
        for (int i = 0; i < 32; ++i)
            g_aq1[(size_t)(bt0 + i) * VD_ + c] = fmaxf(acc[i] + bias, 0.f);
    }

    // aq2: 256 outputs, 1 per thread
    {
        int j = tid;
        const float4* w4 = (const float4*)(Wa2 + (size_t)j * AD_);
        float acc[32];
#pragma unroll
        for (int i = 0; i < 32; ++i) acc[i] = 0.f;
        for (int k4 = 0; k4 < AD_ / 4; ++k4) {
            float4 w = w4[k4];
#pragma unroll
            for (int i = 0; i < 32; ++i) {
                float4 v = *(const float4*)&af[i][k4 * 4];
                acc[i] += v.x * w.x + v.y * w.y + v.z * w.z + v.w * w.w;
            }
        }
        float bias = ba2[j];
#pragma unroll
        for (int i = 0; i < 32; ++i)
            g_aq2[(size_t)(bt0 + i) * HD_ + j] = fmaxf(acc[i] + bias, 0.f);
    }
}

// ---------------------------------------------------------------------------
// K2: big GEMM #1 fused with hw-mean of relu.
//   grid = (2, BT_), block = 256. blockIdx.x selects channel half.
//   Each thread: one output channel c, 49 k-paired f32x2 accumulators.
//   g_m1[bt,c] = g_aq1[bt,c] * (1/49) * sum_hw relu(vf[hw,:]·Wv1[c,:] + bv1[c])
// ---------------------------------------------------------------------------
__global__ void __launch_bounds__(256)
k2_vq1(const float* __restrict__ video,
       const float* __restrict__ Wv1, const float* __restrict__ bv1)
{
    extern __shared__ float sm[];
    const int tid = threadIdx.x;
    const int bt = blockIdx.y;
    const int c = blockIdx.x * 256 + tid;

    // stage vf tile [49][512] fp32 into smem
    const float4* src = (const float4*)(video + (size_t)bt * HW_ * VD_);
    float4* dst = (float4*)sm;
    for (int i = tid; i < HW_ * VD_ / 4; i += 256) dst[i] = src[i];
    __syncthreads();

    const ulonglong2* w2 = (const ulonglong2*)(Wv1 + (size_t)c * VD_);
    const ulonglong2* v2 = (const ulonglong2*)sm;

    unsigned long long acc[HW_];
#pragma unroll
    for (int h = 0; h < HW_; ++h) acc[h] = 0ull;

#pragma unroll 1
    for (int k = 0; k < VD_ / 4; ++k) {
        ulonglong2 w = w2[k];
#pragma unroll
        for (int h = 0; h < HW_; ++h) {
            ulonglong2 v = v2[h * (VD_ / 4) + k];
            acc[h] = ffma2(v.x, w.x, acc[h]);
            acc[h] = ffma2(v.y, w.y, acc[h]);
        }
    }

    float bias = bv1[c];
    float s = 0.f;
#pragma unroll
    for (int h = 0; h < HW_; ++h)
        s += fmaxf(lo32(acc[h]) + hi32(acc[h]) + bias, 0.f);

    g_m1[(size_t)bt * VD_ + c] =
        g_aq1[(size_t)bt * VD_ + c] * s * (1.f / 49.f);
}

// ---------------------------------------------------------------------------
// K3: channel-attention MLP. 8 clips per block, 256 threads.
//   t1 = relu(m1 @ Wb^T + bb)          [*,256]
//   g_scale = sigmoid(t1 @ Wc^T + bc)+1  [*,512]
// ---------------------------------------------------------------------------
__global__ void __launch_bounds__(256)
k3_catt(const float* __restrict__ Wb, const float* __restrict__ bb,
        const float* __restrict__ Wc, const float* __restrict__ bc)
{
    __shared__ __align__(16) float m1s[8][VD_];
    __shared__ __align__(16) float t1s[8][HD_];
    const int tid = threadIdx.x;
    const int bt0 = blockIdx.x * 8;

    {
        const float4* src = (const float4*)(g_m1 + (size_t)bt0 * VD_);
        float4* dst = (float4*)m1s;
        for (int i = tid; i < 8 * VD_ / 4; i += 256) dst[i] = src[i];
    }
    __syncthreads();

    // stage 1: 256 outputs j
    {
        int j = tid;
        const float4* w4 = (const float4*)(Wb + (size_t)j * VD_);
        float acc[8];
#pragma unroll
        for (int i = 0; i < 8; ++i) acc[i] = 0.f;
        for (int k4 = 0; k4 < VD_ / 4; ++k4) {
            float4 w = w4[k4];
#pragma unroll
            for (int i = 0; i < 8; ++i) {
                float4 v = *(const float4*)&m1s[i][k4 * 4];
                acc[i] += v.x * w.x + v.y * w.y + v.z * w.z + v.w * w.w;
            }
        }
        float bias = bb[j];
#pragma unroll
        for (int i = 0; i < 8; ++i) t1s[i][j] = fmaxf(acc[i] + bias, 0.f);
    }
    __syncthreads();

    // stage 2: 512 outputs c
    for (int c = tid; c < VD_; c += 256) {
        const float4* w4 = (const float4*)(Wc + (size_t)c * HD_);
        float acc[8];
#pragma unroll
        for (int i = 0; i < 8; ++i) acc[i] = 0.f;
        for (int k4 = 0; k4 < HD_ / 4; ++k4) {
            float4 w = w4[k4];
#pragma unroll
            for (int i = 0; i < 8; ++i) {
                float4 v = *(const float4*)&t1s[i][k4 * 4];
                acc[i] += v.x * w.x + v.y * w.y + v.z * w.z + v.w * w.w;
            }
        }
        float bias = bc[c];
#pragma unroll
        for (int i = 0; i < 8; ++i) {
            float x = acc[i] + bias;
            g_scale[(size_t)(bt0 + i) * VD_ + c] = 1.f + 1.f / (1.f + expf(-x));
        }
    }
}

// ---------------------------------------------------------------------------
// K4: spatial attention + output, fully fused per clip. grid = BT_, block 256.
//   catt[hw,c] = vf[hw,c]*scale[c]                   (staged in smem)
//   cq[hw,j]   = relu(catt[hw,:]·Wv2[j,:] + bv2[j])
//   l[hw]      = tanh(sum_j cq[hw,j]*aq2[j]*Ws[j] + bs)
//   w_att      = softmax_hw(l)
//   out[c]     = sum_hw w_att[hw]*catt[hw,c]
// ---------------------------------------------------------------------------
#define PART_STRIDE 51   // odd stride: conflict-free partial buffer

__global__ void __launch_bounds__(256)
k4_spatial(const float* __restrict__ video,
           const float* __restrict__ Wv2, const float* __restrict__ bv2,
           const float* __restrict__ Ws,  const float* __restrict__ bs,
           float* __restrict__ out)
{
    extern __shared__ float sm[];
    float* catt = sm;                          // 49*512 = 25088 floats
    float* part = sm + HW_ * VD_;              // 256*51 = 13056 floats
    float* red  = part + 256 * PART_STRIDE;    // 64 floats

    const int tid = threadIdx.x;
    const int bt = blockIdx.x;

    // stage catt = vf * scale
    {
        const float4* src = (const float4*)(video + (size_t)bt * HW_ * VD_);
        const float4* sc4 = (const float4*)(g_scale + (size_t)bt * VD_);
        float4* dst = (float4*)catt;
        for (int i = tid; i < HW_ * VD_ / 4; i += 256) {
            float4 v = src[i];
            float4 s = sc4[i & (VD_ / 4 - 1)];
            v.x *= s.x; v.y *= s.y; v.z *= s.z; v.w *= s.w;
            dst[i] = v;
        }
    }
    __syncthreads();

    // cq GEMM: thread j owns one of 256 outputs, 49 f32x2 accumulators
    {
        const int j = tid;
        const ulonglong2* w2 = (const ulonglong2*)(Wv2 + (size_t)j * VD_);
        const ulonglong2* v2 = (const ulonglong2*)catt;

        unsigned long long acc[HW_];
#pragma unroll
        for (int h = 0; h < HW_; ++h) acc[h] = 0ull;

#pragma unroll 1
        for (int k = 0; k < VD_ / 4; ++k) {
            ulonglong2 w = w2[k];
#pragma unroll
            for (int h = 0; h < HW_; ++h) {
                ulonglong2 v = v2[h * (VD_ / 4) + k];
                acc[h] = ffma2(v.x, w.x, acc[h]);
                acc[h] = ffma2(v.y, w.y, acc[h]);
            }
        }

        float bias = bv2[j];
        float u = g_aq2[(size_t)bt * HD_ + j] * Ws[j];
#pragma unroll
        for (int h = 0; h < HW_; ++h)
            part[j * PART_STRIDE + h] =
                fmaxf(lo32(acc[h]) + hi32(acc[h]) + bias, 0.f) * u;
    }
    __syncthreads();

    // logits: reduce over j (threads 0..48, conflict-free column reads)
    if (tid < HW_) {
        float s = 0.f;
        for (int jj = 0; jj < 256; ++jj) s += part[jj * PART_STRIDE + tid];
        red[tid] = tanhf(s + bs[0]);
    }
    __syncthreads();

    if (tid == 0) {
        float mx = -1e30f;
        for (int h = 0; h < HW_; ++h) mx = fmaxf(mx, red[h]);
        float den = 0.f;
        for (int h = 0; h < HW_; ++h) den += expf(red[h] - mx);
        red[HW_]     = mx;
        red[HW_ + 1] = den;
    }
    __syncthreads();

    if (tid < HW_) red[tid] = expf(red[tid] - red[HW_]) / red[HW_ + 1];
    __syncthreads();

    // out[c] = sum_hw w_att[hw] * catt[hw,c]
    for (int c = tid; c < VD_; c += 256) {
        float acc = 0.f;
#pragma unroll
        for (int h = 0; h < HW_; ++h) acc += red[h] * catt[h * VD_ + c];
        out[(size_t)bt * VD_ + c] = acc;
    }
}

// ---------------------------------------------------------------------------
// Launch
// ---------------------------------------------------------------------------
extern "C" void kernel_launch(void* const* d_in, const int* in_sizes, int n_in,
                              void* d_out, int out_size)
{
    const float* video = (const float*)d_in[0];
    const float* audio = (const float*)d_in[1];
    const float* Wv1   = (const float*)d_in[2];
    const float* bv1   = (const float*)d_in[3];
    const float* Wa1   = (const float*)d_in[4];
    const float* ba1   = (const float*)d_in[5];
    const float* Wb    = (const float*)d_in[6];
    const float* bb    = (const float*)d_in[7];
    const float* Wc    = (const float*)d_in[8];
    const float* bc    = (const float*)d_in[9];
    const float* Wv2   = (const float*)d_in[10];
    const float* bv2   = (const float*)d_in[11];
    const float* Wa2   = (const float*)d_in[12];
    const float* ba2   = (const float*)d_in[13];
    const float* Ws    = (const float*)d_in[14];
    const float* bs    = (const float*)d_in[15];
    float* out = (float*)d_out;

    const int smem2 = HW_ * VD_ * 4;                              // 100352 B
    const int smem4 = (HW_ * VD_ + 256 * PART_STRIDE + 64) * 4;   // 152832 B
    cudaFuncSetAttribute(k2_vq1,     cudaFuncAttributeMaxDynamicSharedMemorySize, smem2);
    cudaFuncSetAttribute(k4_spatial, cudaFuncAttributeMaxDynamicSharedMemorySize, smem4);

    k1_audio<<<BT_ / 32, 256>>>(audio, Wa1, ba1, Wa2, ba2);
    k2_vq1<<<dim3(2, BT_), 256, smem2>>>(video, Wv1, bv1);
    k3_catt<<<BT_ / 8, 256>>>(Wb, bb, Wc, bc);
    k4_spatial<<<BT_, 256, smem4>>>(video, Wv2, bv2, Ws, bs, out);
}

// round 7
// speedup vs baseline: 2.6188x; 2.6188x over previous
#include <cuda_runtime.h>
#include <cuda_bf16.h>
#include <cstdint>

#define B_   256
#define T_   10
#define BT_  2560
#define HW_  49
#define VD_  512
#define AD_  128
#define HD_  256

// ---------------------------------------------------------------------------
// Scratch (__device__ globals — allocation-free)
// ---------------------------------------------------------------------------
__device__ float g_aq1[BT_ * VD_];
__device__ float g_aq2[BT_ * HD_];
__device__ float g_m1 [BT_ * VD_];
__device__ float g_scale[BT_ * VD_];
__device__ float g_part[BT_ * 2 * 64];   // per-clip, per-n-half row partials

// Pre-split, pre-padded bf16 weight images, laid out exactly as the SMEM tile:
// [n_chunk][k_chunk(8)][128 n-rows][72 k-elems]  (72 = 64 + 8 pad for ldmatrix)
__device__ __align__(16) __nv_bfloat16 g_W1h[4 * 8 * 128 * 72];
__device__ __align__(16) __nv_bfloat16 g_W1l[4 * 8 * 128 * 72];
__device__ __align__(16) __nv_bfloat16 g_W2h[2 * 8 * 128 * 72];
__device__ __align__(16) __nv_bfloat16 g_W2l[2 * 8 * 128 * 72];

#define CHUNK_ELEMS (128 * 72)          // 9216 bf16 = 18432 B
#define ROWB 144                        // 72 bf16 per row
#define MT_STRIDE (16 * ROWB)           // 2304 B per 16-row tile

// ---------------------------------------------------------------------------
// Helpers (plain sm_103-safe PTX only: ldmatrix, mma.sync, cp.async)
// ---------------------------------------------------------------------------
__device__ __forceinline__ uint32_t smem_u32(const void* p) {
    uint32_t a;
    asm("{ .reg .u64 t; cvta.to.shared.u64 t, %1; cvt.u32.u64 %0, t; }"
        : "=r"(a) : "l"(p));
    return a;
}

__device__ __forceinline__ void ldmx4(uint32_t addr, uint32_t r[4]) {
    asm volatile("ldmatrix.sync.aligned.m8n8.x4.shared.b16 {%0,%1,%2,%3}, [%4];"
                 : "=r"(r[0]), "=r"(r[1]), "=r"(r[2]), "=r"(r[3]) : "r"(addr));
}

__device__ __forceinline__ void mma_bf16(float d[4], const uint32_t a[4],
                                         uint32_t b0, uint32_t b1) {
    asm volatile(
        "mma.sync.aligned.m16n8k16.row.col.f32.bf16.bf16.f32 "
        "{%0,%1,%2,%3},{%4,%5,%6,%7},{%8,%9},{%0,%1,%2,%3};"
        : "+f"(d[0]), "+f"(d[1]), "+f"(d[2]), "+f"(d[3])
        : "r"(a[0]), "r"(a[1]), "r"(a[2]), "r"(a[3]), "r"(b0), "r"(b1));
}

__device__ __forceinline__ void cp16(uint32_t dst, const void* src) {
    asm volatile("cp.async.cg.shared.global [%0], [%1], 16;" :: "r"(dst), "l"(src));
}
__device__ __forceinline__ void cp_commit_wait() {
    asm volatile("cp.async.commit_group;" ::: "memory");
    asm volatile("cp.async.wait_group 0;" ::: "memory");
}

__device__ __forceinline__ void split_store(char* Ah, char* Al, int r, int q,
                                            float x0, float x1, float x2, float x3) {
    __nv_bfloat16 h0 = __float2bfloat16(x0), h1 = __float2bfloat16(x1);
    __nv_bfloat16 h2 = __float2bfloat16(x2), h3 = __float2bfloat16(x3);
    __nv_bfloat16 l0 = __float2bfloat16(x0 - __bfloat162float(h0));
    __nv_bfloat16 l1 = __float2bfloat16(x1 - __bfloat162float(h1));
    __nv_bfloat16 l2 = __float2bfloat16(x2 - __bfloat162float(h2));
    __nv_bfloat16 l3 = __float2bfloat16(x3 - __bfloat162float(h3));
    __nv_bfloat162 p;
    char* dh = Ah + r * ROWB + q * 8;
    char* dl = Al + r * ROWB + q * 8;
    p.x = h0; p.y = h1; *(__nv_bfloat162*)dh = p;
    p.x = h2; p.y = h3; *(__nv_bfloat162*)(dh + 4) = p;
    p.x = l0; p.y = l1; *(__nv_bfloat162*)dl = p;
    p.x = l2; p.y = l3; *(__nv_bfloat162*)(dl + 4) = p;
}

// ---------------------------------------------------------------------------
// k0: split Wv1/Wv2 into bf16 hi/lo padded tile images
// ---------------------------------------------------------------------------
__global__ void __launch_bounds__(256)
k0_wconv(const float* __restrict__ Wv1, const float* __restrict__ Wv2)
{
    int idx = blockIdx.x * 256 + threadIdx.x;
    if (idx < 512 * 512) {
        int c = idx >> 9, k = idx & 511;
        float v = Wv1[idx];
        __nv_bfloat16 h = __float2bfloat16(v);
        __nv_bfloat16 l = __float2bfloat16(v - __bfloat162float(h));
        int nc = c >> 7, nl = c & 127, kc = k >> 6, kk = k & 63;
        size_t d = ((size_t)(nc * 8 + kc) * 128 + nl) * 72 + kk;
        g_W1h[d] = h; g_W1l[d] = l;
    } else if (idx < 512 * 512 + 256 * 512) {
        int e = idx - 512 * 512;
        int j = e >> 9, k = e & 511;
        float v = Wv2[e];
        __nv_bfloat16 h = __float2bfloat16(v);
        __nv_bfloat16 l = __float2bfloat16(v - __bfloat162float(h));
        int nc = j >> 7, nl = j & 127, kc = k >> 6, kk = k & 63;
        size_t d = ((size_t)(nc * 8 + kc) * 128 + nl) * 72 + kk;
        g_W2h[d] = h; g_W2l[d] = l;
    }
}

// ---------------------------------------------------------------------------
// k1: audio features (unchanged from passing R5 version)
// ---------------------------------------------------------------------------
__global__ void __launch_bounds__(256)
k1_audio(const float* __restrict__ audio,
         const float* __restrict__ Wa1, const float* __restrict__ ba1,
         const float* __restrict__ Wa2, const float* __restrict__ ba2)
{
    __shared__ __align__(16) float af[32][AD_];
    const int tid = threadIdx.x;
    const int bt0 = blockIdx.x * 32;

    for (int idx = tid; idx < 32 * AD_; idx += 256) {
        int i = idx >> 7, k = idx & 127;
        int bt = bt0 + i;
        int b = bt / T_, t = bt - b * T_;
        af[i][k] = audio[((size_t)t * B_ + b) * AD_ + k];
    }
    __syncthreads();

    for (int c = tid; c < VD_; c += 256) {
        const float4* w4 = (const float4*)(Wa1 + (size_t)c * AD_);
        float acc[32];
#pragma unroll
        for (int i = 0; i < 32; ++i) acc[i] = 0.f;
        for (int k4 = 0; k4 < AD_ / 4; ++k4) {
            float4 w = w4[k4];
#pragma unroll
            for (int i = 0; i < 32; ++i) {
                float4 v = *(const float4*)&af[i][k4 * 4];
                acc[i] += v.x * w.x + v.y * w.y + v.z * w.z + v.w * w.w;
            }
        }
        float bias = ba1[c];
#pragma unroll
        for (int i = 0; i < 32; ++i)
            g_aq1[(size_t)(bt0 + i) * VD_ + c] = fmaxf(acc[i] + bias, 0.f);
    }
    {
        int j = tid;
        const float4* w4 = (const float4*)(Wa2 + (size_t)j * AD_);
        float acc[32];
#pragma unroll
        for (int i = 0; i < 32; ++i) acc[i] = 0.f;
        for (int k4 = 0; k4 < AD_ / 4; ++k4) {
            float4 w = w4[k4];
#pragma unroll
            for (int i = 0; i < 32; ++i) {
                float4 v = *(const float4*)&af[i][k4 * 4];
                acc[i] += v.x * w.x + v.y * w.y + v.z * w.z + v.w * w.w;
            }
        }
        float bias = ba2[j];
#pragma unroll
        for (int i = 0; i < 32; ++i)
            g_aq2[(size_t)(bt0 + i) * HD_ + j] = fmaxf(acc[i] + bias, 0.f);
    }
}

// ---------------------------------------------------------------------------
// Shared GEMM mainloop. Block = M64 (one clip, rows 0..48 + pad) x N128.
// 8 warps as 2(M) x 4(N); each warp M32 x N32. acc[2 mt][4 nt][4].
// SMEM layout (dynamic, 55296 B):
//   A_h @0 (9216B)  A_l @9216  W_h @18432 (18432B)  W_l @36864
// ---------------------------------------------------------------------------
__device__ __forceinline__ void gemm_mainloop(
    float acc[2][4][4], char* sm, uint32_t aBase,
    const float* __restrict__ video, const float* scale /*nullptr or per-clip*/,
    const __nv_bfloat16* wImgH, const __nv_bfloat16* wImgL,
    int bt, int tid, int lane, int wm, int wn)
{
    char* A_h = sm;
    char* A_l = sm + 9216;

    // zero pad rows 49..63 of A (hi+lo), once
    for (int i = tid; i < 540; i += 256) {
        int r = 49 + i / 36, o = (i % 36) * 4;
        *(uint32_t*)(A_h + r * ROWB + o) = 0u;
        *(uint32_t*)(A_l + r * ROWB + o) = 0u;
    }

    // per-lane ldmatrix base addresses
    const uint32_t pAh = aBase + (uint32_t)((wm * 32 + (lane & 15)) * ROWB
                        + ((lane >> 4) & 1) * 16);
    const uint32_t pAl = pAh + 9216;
    const uint32_t pBh = aBase + 18432u
                        + (uint32_t)((wn * 32 + (lane & 7) + ((lane >> 4) & 1) * 8) * ROWB
                        + ((lane >> 3) & 1) * 16);
    const uint32_t pBl = pBh + 18432;

    for (int kc = 0; kc < 8; ++kc) {
        __syncthreads();   // previous chunk's ldmatrix reads done before overwrite
        // W chunk: flat async copy of pre-padded image
        {
            const char* sH = (const char*)(wImgH + (size_t)kc * CHUNK_ELEMS);
            const char* sL = (const char*)(wImgL + (size_t)kc * CHUNK_ELEMS);
            for (int off = tid * 16; off < 18432; off += 4096) {
                cp16(aBase + 18432 + off, sH + off);
                cp16(aBase + 36864 + off, sL + off);
            }
        }
        // A chunk: convert 49 x 64 fp32 -> bf16 hi/lo (optionally x scale)
        for (int idx = tid; idx < 49 * 16; idx += 256) {
            int r = idx >> 4, q = idx & 15;
            float4 v = *(const float4*)(video +
                ((size_t)bt * HW_ + r) * VD_ + kc * 64 + q * 4);
            if (scale) {
                float4 s = *(const float4*)(scale + kc * 64 + q * 4);
                v.x *= s.x; v.y *= s.y; v.z *= s.z; v.w *= s.w;
            }
            split_store(A_h, A_l, r, q, v.x, v.y, v.z, v.w);
        }
        cp_commit_wait();
        __syncthreads();

#pragma unroll
        for (int ks = 0; ks < 4; ++ks) {
            uint32_t ah[2][4], al[2][4], bh[2][4], bl[2][4];
#pragma unroll
            for (int mt = 0; mt < 2; ++mt) {
                ldmx4(pAh + mt * MT_STRIDE + ks * 32, ah[mt]);
                ldmx4(pAl + mt * MT_STRIDE + ks * 32, al[mt]);
            }
#pragma unroll
            for (int np = 0; np < 2; ++np) {
                ldmx4(pBh + np * MT_STRIDE + ks * 32, bh[np]);
                ldmx4(pBl + np * MT_STRIDE + ks * 32, bl[np]);
            }
#pragma unroll
            for (int mt = 0; mt < 2; ++mt)
#pragma unroll
                for (int nt = 0; nt < 4; ++nt) {
                    int np = nt >> 1, s = (nt & 1) * 2;
                    mma_bf16(acc[mt][nt], ah[mt], bh[np][s], bh[np][s + 1]);
                    mma_bf16(acc[mt][nt], al[mt], bh[np][s], bh[np][s + 1]);
                    mma_bf16(acc[mt][nt], ah[mt], bl[np][s], bl[np][s + 1]);
                }
        }
    }
    __syncthreads();   // mainloop done; smem free for epilogue reuse
}

// ---------------------------------------------------------------------------
// g1: GEMM1 + relu + hw-mean + x aq1/49 -> g_m1.  grid = (4 n-chunks, 2560)
// ---------------------------------------------------------------------------
__global__ void __launch_bounds__(256, 2)
g1_mma(const float* __restrict__ video, const float* __restrict__ bv1)
{
    extern __shared__ char sm[];
    const int tid = threadIdx.x, wid = tid >> 5, lane = tid & 31;
    const int wm = wid >> 2, wn = wid & 3;
    const int nc = blockIdx.x, bt = blockIdx.y;
    const uint32_t aBase = smem_u32(sm);

    float acc[2][4][4];
#pragma unroll
    for (int a = 0; a < 2; ++a)
#pragma unroll
        for (int b = 0; b < 4; ++b)
#pragma unroll
            for (int c = 0; c < 4; ++c) acc[a][b][c] = 0.f;

    gemm_mainloop(acc, sm, aBase, video, nullptr,
                  g_W1h + (size_t)nc * 8 * CHUNK_ELEMS,
                  g_W1l + (size_t)nc * 8 * CHUNK_ELEMS,
                  bt, tid, lane, wm, wn);

    // stage relu(D + bias) into smem [64][132]
    float* stage = (float*)sm;
#pragma unroll
    for (int mt = 0; mt < 2; ++mt)
#pragma unroll
        for (int nt = 0; nt < 4; ++nt) {
            int r0 = wm * 32 + mt * 16 + (lane >> 2);
            int c0 = wn * 32 + nt * 8 + (lane & 3) * 2;
            float b0 = bv1[nc * 128 + c0], b1 = bv1[nc * 128 + c0 + 1];
            stage[r0 * 132 + c0]           = fmaxf(acc[mt][nt][0] + b0, 0.f);
            stage[r0 * 132 + c0 + 1]       = fmaxf(acc[mt][nt][1] + b1, 0.f);
            stage[(r0 + 8) * 132 + c0]     = fmaxf(acc[mt][nt][2] + b0, 0.f);
            stage[(r0 + 8) * 132 + c0 + 1] = fmaxf(acc[mt][nt][3] + b1, 0.f);
        }
    __syncthreads();

    if (tid < 128) {
        float s = 0.f;
#pragma unroll
        for (int h = 0; h < HW_; ++h) s += stage[h * 132 + tid];
        int c = nc * 128 + tid;
        g_m1[(size_t)bt * VD_ + c] =
            g_aq1[(size_t)bt * VD_ + c] * s * (1.f / 49.f);
    }
}

// ---------------------------------------------------------------------------
// k3: channel-attention MLP (unchanged from passing R5 version)
// ---------------------------------------------------------------------------
__global__ void __launch_bounds__(256)
k3_catt(const float* __restrict__ Wb, const float* __restrict__ bb,
        const float* __restrict__ Wc, const float* __restrict__ bc)
{
    __shared__ __align__(16) float m1s[8][VD_];
    __shared__ __align__(16) float t1s[8][HD_];
    const int tid = threadIdx.x;
    const int bt0 = blockIdx.x * 8;

    {
        const float4* src = (const float4*)(g_m1 + (size_t)bt0 * VD_);
        float4* dst = (float4*)m1s;
        for (int i = tid; i < 8 * VD_ / 4; i += 256) dst[i] = src[i];
    }
    __syncthreads();
    {
        int j = tid;
        const float4* w4 = (const float4*)(Wb + (size_t)j * VD_);
        float acc[8];
#pragma unroll
        for (int i = 0; i < 8; ++i) acc[i] = 0.f;
        for (int k4 = 0; k4 < VD_ / 4; ++k4) {
            float4 w = w4[k4];
#pragma unroll
            for (int i = 0; i < 8; ++i) {
                float4 v = *(const float4*)&m1s[i][k4 * 4];
                acc[i] += v.x * w.x + v.y * w.y + v.z * w.z + v.w * w.w;
            }
        }
        float bias = bb[j];
#pragma unroll
        for (int i = 0; i < 8; ++i) t1s[i][j] = fmaxf(acc[i] + bias, 0.f);
    }
    __syncthreads();
    for (int c = tid; c < VD_; c += 256) {
        const float4* w4 = (const float4*)(Wc + (size_t)c * HD_);
        float acc[8];
#pragma unroll
        for (int i = 0; i < 8; ++i) acc[i] = 0.f;
        for (int k4 = 0; k4 < HD_ / 4; ++k4) {
            float4 w = w4[k4];
#pragma unroll
            for (int i = 0; i < 8; ++i) {
                float4 v = *(const float4*)&t1s[i][k4 * 4];
                acc[i] += v.x * w.x + v.y * w.y + v.z * w.z + v.w * w.w;
            }
        }
        float bias = bc[c];
#pragma unroll
        for (int i = 0; i < 8; ++i) {
            float x = acc[i] + bias;
            g_scale[(size_t)(bt0 + i) * VD_ + c] = 1.f + 1.f / (1.f + expf(-x));
        }
    }
}

// ---------------------------------------------------------------------------
// g2: GEMM2 (catt @ Wv2^T) + relu x (aq2*Ws) row partials -> g_part
// grid = (2 n-halves, 2560)
// ---------------------------------------------------------------------------
__global__ void __launch_bounds__(256, 2)
g2_mma(const float* __restrict__ video, const float* __restrict__ bv2,
       const float* __restrict__ Ws)
{
    extern __shared__ char sm[];
    __shared__ float u_s[128];
    __shared__ float part[64];
    const int tid = threadIdx.x, wid = tid >> 5, lane = tid & 31;
    const int wm = wid >> 2, wn = wid & 3;
    const int nh = blockIdx.x, bt = blockIdx.y;
    const uint32_t aBase = smem_u32(sm);

    if (tid < 128)
        u_s[tid] = g_aq2[(size_t)bt * HD_ + nh * 128 + tid] * Ws[nh * 128 + tid];
    if (tid < 64) part[tid] = 0.f;

    float acc[2][4][4];
#pragma unroll
    for (int a = 0; a < 2; ++a)
#pragma unroll
        for (int b = 0; b < 4; ++b)
#pragma unroll
            for (int c = 0; c < 4; ++c) acc[a][b][c] = 0.f;

    gemm_mainloop(acc, sm, aBase, video, g_scale + (size_t)bt * VD_,
                  g_W2h + (size_t)nh * 8 * CHUNK_ELEMS,
                  g_W2l + (size_t)nh * 8 * CHUNK_ELEMS,
                  bt, tid, lane, wm, wn);

    // row partials: sum_j relu(D + bv2[j]) * u[j]
#pragma unroll
    for (int mt = 0; mt < 2; ++mt) {
        int r0 = wm * 32 + mt * 16 + (lane >> 2);
        float s0 = 0.f, s1 = 0.f;
#pragma unroll
        for (int nt = 0; nt < 4; ++nt) {
            int c0 = wn * 32 + nt * 8 + (lane & 3) * 2;
            float b0 = bv2[nh * 128 + c0], b1 = bv2[nh * 128 + c0 + 1];
            float u0 = u_s[c0], u1 = u_s[c0 + 1];
            s0 += fmaxf(acc[mt][nt][0] + b0, 0.f) * u0
                + fmaxf(acc[mt][nt][1] + b1, 0.f) * u1;
            s1 += fmaxf(acc[mt][nt][2] + b0, 0.f) * u0
                + fmaxf(acc[mt][nt][3] + b1, 0.f) * u1;
        }
        s0 += __shfl_xor_sync(0xffffffffu, s0, 1);
        s0 += __shfl_xor_sync(0xffffffffu, s0, 2);
        s1 += __shfl_xor_sync(0xffffffffu, s1, 1);
        s1 += __shfl_xor_sync(0xffffffffu, s1, 2);
        if ((lane & 3) == 0) {
            atomicAdd(&part[r0], s0);
            atomicAdd(&part[r0 + 8], s1);
        }
    }
    __syncthreads();
    if (tid < 64)
        g_part[((size_t)bt * 2 + nh) * 64 + tid] = part[tid];
}

// ---------------------------------------------------------------------------
// k5: tanh + softmax + output contraction.  grid = 2560, 128 threads
// ---------------------------------------------------------------------------
__global__ void __launch_bounds__(128)
k5_out(const float* __restrict__ video, const float* __restrict__ bs,
       float* __restrict__ out)
{
    __shared__ float swt[64];
    __shared__ float smx, sdn;
    const int tid = threadIdx.x;
    const int bt = blockIdx.x;

    if (tid < HW_)
        swt[tid] = tanhf(g_part[((size_t)bt * 2) * 64 + tid]
                       + g_part[((size_t)bt * 2 + 1) * 64 + tid] + bs[0]);
    __syncthreads();
    if (tid == 0) {
        float mx = -1e30f;
        for (int h = 0; h < HW_; ++h) mx = fmaxf(mx, swt[h]);
        float den = 0.f;
        for (int h = 0; h < HW_; ++h) den += expf(swt[h] - mx);
        smx = mx; sdn = den;
    }
    __syncthreads();
    if (tid < HW_) swt[tid] = expf(swt[tid] - smx) / sdn;
    __syncthreads();

    for (int c = tid; c < VD_; c += 128) {
        float a = 0.f;
#pragma unroll 7
        for (int h = 0; h < HW_; ++h)
            a += swt[h] * video[((size_t)bt * HW_ + h) * VD_ + c];
        out[(size_t)bt * VD_ + c] = a * g_scale[(size_t)bt * VD_ + c];
    }
}

// ---------------------------------------------------------------------------
// Launch
// ---------------------------------------------------------------------------
extern "C" void kernel_launch(void* const* d_in, const int* in_sizes, int n_in,
                              void* d_out, int out_size)
{
    const float* video = (const float*)d_in[0];
    const float* audio = (const float*)d_in[1];
    const float* Wv1   = (const float*)d_in[2];
    const float* bv1   = (const float*)d_in[3];
    const float* Wa1   = (const float*)d_in[4];
    const float* ba1   = (const float*)d_in[5];
    const float* Wb    = (const float*)d_in[6];
    const float* bb    = (const float*)d_in[7];
    const float* Wc    = (const float*)d_in[8];
    const float* bc    = (const float*)d_in[9];
    const float* Wv2   = (const float*)d_in[10];
    const float* bv2   = (const float*)d_in[11];
    const float* Wa2   = (const float*)d_in[12];
    const float* ba2   = (const float*)d_in[13];
    const float* Ws    = (const float*)d_in[14];
    const float* bs    = (const float*)d_in[15];
    float* out = (float*)d_out;

    const int smem = 55296;   // A hi/lo 18432 + W hi/lo 36864
    cudaFuncSetAttribute(g1_mma, cudaFuncAttributeMaxDynamicSharedMemorySize, smem);
    cudaFuncSetAttribute(g2_mma, cudaFuncAttributeMaxDynamicSharedMemorySize, smem);

    k0_wconv<<<1536, 256>>>(Wv1, Wv2);
    k1_audio<<<BT_ / 32, 256>>>(audio, Wa1, ba1, Wa2, ba2);
    g1_mma<<<dim3(4, BT_), 256, smem>>>(video, bv1);
    k3_catt<<<BT_ / 8, 256>>>(Wb, bb, Wc, bc);
    g2_mma<<<dim3(2, BT_), 256, smem>>>(video, bv2, Ws);
    k5_out<<<BT_, 128>>>(video, bs, out);
}